// round 4
// baseline (speedup 1.0000x reference)
#include <cuda_runtime.h>
#include <cstdint>

#define NN   50000
#define EE   800000
#define INF  128
#define HF   128
#define RR   8
#define OUTF 2
#define BN_EPS 1e-5f
#define GEMM_TILES ((NN + 127) / 128)   // 391

// ---------------- scratch (device globals; no allocation allowed) ----------
__device__ float g_xw[(size_t)RR * NN * HF];   // [R][N][H] transformed features
__device__ float g_agg[(size_t)NN * HF];       // pre-BN layer output
__device__ float g_xhi[(size_t)NN * HF];       // tf32 hi split of activations
__device__ float g_xlo[(size_t)NN * HF];       // tf32 lo split
__device__ float g_whi[9 * 128 * 128];         // [mat][n][k] transposed weights, hi
__device__ float g_wlo[9 * 128 * 128];         // lo
__device__ int   g_deg[NN * RR];
__device__ float g_sum[HF];
__device__ float g_sumsq[HF];
// edge bucketing (by relation type)
__device__ int   g_tcnt[RR];        // counts, then running cursors
__device__ int   g_tbase[RR + 1];
__device__ int   g_epack[EE];       // src | (type<<16)   (src < 65536)
__device__ int   g_etgt[EE];

// ======================= small helpers ======================================
__device__ __forceinline__ uint32_t smem_to_u32(const void* p) {
    uint32_t a;
    asm("{ .reg .u64 t; cvta.to.shared.u64 t, %1; cvt.u32.u64 %0, t; }"
        : "=r"(a) : "l"(p));
    return a;
}
__device__ __forceinline__ float tf32r(float x) {
    uint32_t u;
    asm("cvt.rna.tf32.f32 %0, %1;" : "=r"(u) : "f"(x));
    return __uint_as_float(u);
}
__device__ __forceinline__ void cp16(uint32_t dst, const float* src) {
    asm volatile("cp.async.cg.shared.global [%0], [%1], 16;"
                 :: "r"(dst), "l"(__cvta_generic_to_global(src)));
}
__device__ __forceinline__ void mma_tf32(float d[4], uint32_t a[4], uint32_t b[2]) {
    asm volatile(
        "mma.sync.aligned.m16n8k8.row.col.f32.tf32.tf32.f32 "
        "{%0,%1,%2,%3}, {%4,%5,%6,%7}, {%8,%9}, {%0,%1,%2,%3};"
        : "+f"(d[0]), "+f"(d[1]), "+f"(d[2]), "+f"(d[3])
        : "r"(a[0]), "r"(a[1]), "r"(a[2]), "r"(a[3]), "r"(b[0]), "r"(b[1]));
}

// =============== SMEM layout (float offsets), stride-132 pad ================
#define SA     132
#define AH_F   0
#define AL_F   (128 * SA)                 // 16896
#define B0_F   (2 * 128 * SA)             // 33792
#define B1_F   (B0_F + 64 * SA)           // 42240
#define SMEM_FLOATS (B1_F + 64 * SA)      // 50688
#define SMEM_BYTES  (SMEM_FLOATS * 4)     // 202752

// prefetch one 64x128 B tile (row-major [n][k]) into padded smem via cp.async
__device__ __forceinline__ void prefetch_B(uint32_t sb, int bofs_f, const float* W) {
    int tid = threadIdx.x;
#pragma unroll
    for (int i = 0; i < 16; i++) {
        int e = i * 128 + tid;            // 0..2047 float4s
        int row = e >> 5;                 // 0..63
        int q   = e & 31;
        cp16(sb + (uint32_t)(bofs_f + row * SA + q * 4) * 4, W + row * 128 + q * 4);
    }
}

// one 3xTF32 partial pass: D += A(smem) x B(smem)^T over K=128
__device__ __forceinline__ void do_pass(const float* __restrict__ As,
                                        const float* __restrict__ Bs,
                                        float d[4][4][4], int wm, int wn,
                                        int lr, int lc) {
#pragma unroll 4
    for (int ks = 0; ks < 16; ks++) {
        int k0 = ks * 8;
        uint32_t a[4][4], b[4][2];
#pragma unroll
        for (int mt = 0; mt < 4; mt++) {
            const float* p = As + (wm * 64 + mt * 16 + lr) * SA + k0 + lc;
            a[mt][0] = __float_as_uint(p[0]);
            a[mt][1] = __float_as_uint(p[8 * SA]);
            a[mt][2] = __float_as_uint(p[4]);
            a[mt][3] = __float_as_uint(p[8 * SA + 4]);
        }
#pragma unroll
        for (int nt = 0; nt < 4; nt++) {
            const float* p = Bs + (wn * 32 + nt * 8 + lr) * SA + k0 + lc;
            b[nt][0] = __float_as_uint(p[0]);
            b[nt][1] = __float_as_uint(p[4]);
        }
#pragma unroll
        for (int mt = 0; mt < 4; mt++)
#pragma unroll
            for (int nt = 0; nt < 4; nt++) mma_tf32(d[mt][nt], a[mt], b[nt]);
    }
}

// ================== tensor-core GEMM: 9 matrices per (M,N)-tile =============
// D[m,n] = sum_k A[m,k] * B[n,k], 3xTF32 (hi*hi + lo*hi + hi*lo).
// grid = (391, 2): x -> 128-row M tile, y -> 64-col N half.
// mats 0..7 -> g_xw[mat]; mat 8 -> g_agg (+bias).
__global__ void __launch_bounds__(128, 1) gemm_tc_kernel(const float* __restrict__ bias) {
    extern __shared__ float smf[];
    uint32_t sb = smem_to_u32(smf);
    const int tid = threadIdx.x;
    const int wid = tid >> 5, lane = tid & 31;
    const int wm = wid & 1, wn = wid >> 1;
    const int lr = lane >> 2, lc = lane & 3;
    const int m0 = blockIdx.x * 128;
    const int nb0 = blockIdx.y * 64;

    // A tiles (hi/lo) resident for whole CTA; zero rows past NN
#pragma unroll 4
    for (int i = 0; i < 32; i++) {
        int e = i * 128 + tid;
        int row = e >> 5, q = e & 31;
        float4 vh = make_float4(0.f, 0.f, 0.f, 0.f), vl = vh;
        if (m0 + row < NN) {
            vh = *reinterpret_cast<const float4*>(g_xhi + (size_t)(m0 + row) * 128 + q * 4);
            vl = *reinterpret_cast<const float4*>(g_xlo + (size_t)(m0 + row) * 128 + q * 4);
        }
        *reinterpret_cast<float4*>(smf + AH_F + row * SA + q * 4) = vh;
        *reinterpret_cast<float4*>(smf + AL_F + row * SA + q * 4) = vl;
    }
    // prologue: prefetch B_hi(mat 0)
    prefetch_B(sb, B0_F, g_whi + nb0 * 128);
    asm volatile("cp.async.commit_group;" ::: "memory");
    asm volatile("cp.async.wait_group 0;" ::: "memory");
    __syncthreads();

    float d[4][4][4];
#pragma unroll
    for (int mt = 0; mt < 4; mt++)
#pragma unroll
        for (int nt = 0; nt < 4; nt++)
#pragma unroll
            for (int j = 0; j < 4; j++) d[mt][nt][j] = 0.f;

    const float* Ah = smf + AH_F;
    const float* Al = smf + AL_F;
    int stage = 0;
    // 18 tiles: even t = B_hi(t/2) [2 passes], odd t = B_lo(t/2) [1 pass]
    for (int t = 0; t < 18; t++) {
        if (t + 1 < 18) {
            int nm = (t + 1) >> 1;
            const float* Wn = ((t + 1) & 1) ? (g_wlo + nm * 16384) : (g_whi + nm * 16384);
            prefetch_B(sb, stage ? B0_F : B1_F, Wn + nb0 * 128);
        }
        asm volatile("cp.async.commit_group;" ::: "memory");

        const float* Bs = smf + (stage ? B1_F : B0_F);
        do_pass(Ah, Bs, d, wm, wn, lr, lc);            // a_hi x b
        if (!(t & 1)) do_pass(Al, Bs, d, wm, wn, lr, lc); // a_lo x b_hi

        if (t & 1) {
            // matrix (t>>1) complete -> store, reset accumulators
            int mat = t >> 1;
            float* gbase = (mat < 8) ? (g_xw + (size_t)mat * NN * HF) : g_agg;
#pragma unroll
            for (int mt = 0; mt < 4; mt++) {
                int r0 = m0 + wm * 64 + mt * 16 + lr;
#pragma unroll
                for (int nt = 0; nt < 4; nt++) {
                    int col = nb0 + wn * 32 + nt * 8 + lc * 2;
                    float b0 = 0.f, b1 = 0.f;
                    if (mat == 8) { b0 = bias[col]; b1 = bias[col + 1]; }
                    if (r0 < NN)
                        *reinterpret_cast<float2*>(gbase + (size_t)r0 * HF + col) =
                            make_float2(d[mt][nt][0] + b0, d[mt][nt][1] + b1);
                    if (r0 + 8 < NN)
                        *reinterpret_cast<float2*>(gbase + (size_t)(r0 + 8) * HF + col) =
                            make_float2(d[mt][nt][2] + b0, d[mt][nt][3] + b1);
#pragma unroll
                    for (int j = 0; j < 4; j++) d[mt][nt][j] = 0.f;
                }
            }
        }
        asm volatile("cp.async.wait_group 0;" ::: "memory");
        __syncthreads();
        stage ^= 1;
    }
}

// ======================= prep kernels ========================================
__global__ void split_x_kernel(const float* __restrict__ x_in) {
    size_t idx = (size_t)blockIdx.x * blockDim.x + threadIdx.x;
    if (idx >= (size_t)NN * HF) return;
    float v = x_in[idx];
    float h = tf32r(v);
    g_xhi[idx] = h;
    g_xlo[idx] = tf32r(v - h);
}

// transpose W[mat][k][n] -> [mat][n][k], split hi/lo. mat 8 = root.
__global__ void split_w_kernel(const float* __restrict__ w, const float* __restrict__ root) {
    int idx = blockIdx.x * blockDim.x + threadIdx.x;
    if (idx >= 9 * 16384) return;
    int mat = idx >> 14;
    int n = (idx >> 7) & 127;
    int k = idx & 127;
    float v = (mat < 8) ? w[(mat << 14) + (k << 7) + n] : root[(k << 7) + n];
    float h = tf32r(v);
    g_whi[idx] = h;
    g_wlo[idx] = tf32r(v - h);
}

// ======================= graph preprocessing =================================
__global__ void zero_deg_sums_kernel() {
    int idx = blockIdx.x * blockDim.x + threadIdx.x;
    if (idx < NN * RR) g_deg[idx] = 0;
    if (idx < HF) { g_sum[idx] = 0.f; g_sumsq[idx] = 0.f; }
    if (idx < RR) g_tcnt[idx] = 0;
}
__global__ void zero_sums_kernel() {
    int idx = threadIdx.x;
    if (idx < HF) { g_sum[idx] = 0.f; g_sumsq[idx] = 0.f; }
}
__global__ void deg_count_kernel(const int* __restrict__ ei, const int* __restrict__ et) {
    int e = blockIdx.x * blockDim.x + threadIdx.x;
    if (e < EE) {
        int tgt = ei[EE + e];
        int t   = et[e];
        atomicAdd(&g_deg[tgt * RR + t], 1);
        atomicAdd(&g_tcnt[t], 1);
    }
}
__global__ void prefix_kernel() {
    if (threadIdx.x == 0) {
        int acc = 0;
        g_tbase[0] = 0;
        for (int r = 0; r < RR; r++) {
            int c = g_tcnt[r];
            acc += c;
            g_tbase[r + 1] = acc;
            g_tcnt[r] = g_tbase[r];   // reset to running cursor
        }
    }
}
__global__ void place_kernel(const int* __restrict__ ei, const int* __restrict__ et) {
    int e = blockIdx.x * blockDim.x + threadIdx.x;
    if (e >= EE) return;
    int src = ei[e];
    int tgt = ei[EE + e];
    int t   = et[e];
    int pos = atomicAdd(&g_tcnt[t], 1);
    g_epack[pos] = src | (t << 16);
    g_etgt[pos]  = tgt;
}

// ---------------- edge scatter: one warp per (type-sorted) edge -------------
__global__ void scatter_kernel() {
    int w = (blockIdx.x * blockDim.x + threadIdx.x) >> 5;
    if (w >= EE) return;
    int lane = threadIdx.x & 31;
    int p   = g_epack[w];
    int src = p & 0xFFFF;
    int t   = p >> 16;
    int tgt = g_etgt[w];
    float inv = 1.0f / (float)g_deg[tgt * RR + t];
    float4 v = *reinterpret_cast<const float4*>(
        g_xw + ((size_t)t * NN + src) * HF + lane * 4);
    float* dst = g_agg + (size_t)tgt * HF + lane * 4;
    asm volatile("red.global.add.v4.f32 [%0], {%1, %2, %3, %4};"
        :: "l"(__cvta_generic_to_global(dst)),
           "f"(v.x * inv), "f"(v.y * inv), "f"(v.z * inv), "f"(v.w * inv)
        : "memory");
}

// ---------------- BN stats / apply ------------------------------------------
__global__ void bn_stats_kernel() {
    int c = threadIdx.x & 127;
    int rstart = blockIdx.x * (blockDim.x >> 7) + (threadIdx.x >> 7);
    int rstep  = gridDim.x * (blockDim.x >> 7);
    float s = 0.f, ss = 0.f;
    for (int r = rstart; r < NN; r += rstep) {
        float v = g_agg[(size_t)r * HF + c];
        s += v;
        ss += v * v;
    }
    atomicAdd(&g_sum[c], s);
    atomicAdd(&g_sumsq[c], ss);
}
// BN + ReLU, emitting tf32 hi/lo splits directly (input to next GEMM / classifier)
__global__ void bn_apply_kernel(const float* __restrict__ gamma,
                                const float* __restrict__ beta) {
    int idx = blockIdx.x * blockDim.x + threadIdx.x;
    if (idx >= NN * HF) return;
    int c = idx & 127;
    const float invN = 1.0f / (float)NN;
    float mean = g_sum[c] * invN;
    float var  = fmaxf(g_sumsq[c] * invN - mean * mean, 0.f);
    float v = (g_agg[idx] - mean) * rsqrtf(var + BN_EPS) * gamma[c] + beta[c];
    v = fmaxf(v, 0.f);
    float h = tf32r(v);
    g_xhi[idx] = h;
    g_xlo[idx] = tf32r(v - h);
}

// ---------------- classifier: out[N,2] = (hi+lo) @ cw + cb ------------------
__global__ void classifier_kernel(const float* __restrict__ cw,
                                  const float* __restrict__ cb,
                                  float* __restrict__ out) {
    __shared__ float wsm[HF * OUTF];
    if (threadIdx.x < HF * OUTF) wsm[threadIdx.x] = cw[threadIdx.x];
    __syncthreads();
    int w = (blockIdx.x * blockDim.x + threadIdx.x) >> 5;
    if (w >= NN) return;
    int lane = threadIdx.x & 31;
    float4 a = *reinterpret_cast<const float4*>(g_xhi + (size_t)w * HF + lane * 4);
    float4 b = *reinterpret_cast<const float4*>(g_xlo + (size_t)w * HF + lane * 4);
    float4 v = make_float4(a.x + b.x, a.y + b.y, a.z + b.z, a.w + b.w);
    int c = lane * 4;
    float o0 = v.x * wsm[(c + 0) * 2]     + v.y * wsm[(c + 1) * 2]
             + v.z * wsm[(c + 2) * 2]     + v.w * wsm[(c + 3) * 2];
    float o1 = v.x * wsm[(c + 0) * 2 + 1] + v.y * wsm[(c + 1) * 2 + 1]
             + v.z * wsm[(c + 2) * 2 + 1] + v.w * wsm[(c + 3) * 2 + 1];
#pragma unroll
    for (int off = 16; off > 0; off >>= 1) {
        o0 += __shfl_down_sync(0xFFFFFFFFu, o0, off);
        o1 += __shfl_down_sync(0xFFFFFFFFu, o1, off);
    }
    if (lane == 0) {
        out[(size_t)w * 2 + 0] = o0 + cb[0];
        out[(size_t)w * 2 + 1] = o1 + cb[1];
    }
}

// ================================ launch =====================================
extern "C" void kernel_launch(void* const* d_in, const int* in_sizes, int n_in,
                              void* d_out, int out_size) {
    const float* x    = (const float*)d_in[0];
    const int*   ei   = (const int*)d_in[1];
    const int*   et   = (const int*)d_in[2];
    const float* w1   = (const float*)d_in[3];
    const float* r1   = (const float*)d_in[4];
    const float* b1   = (const float*)d_in[5];
    const float* g1   = (const float*)d_in[6];
    const float* be1  = (const float*)d_in[7];
    const float* w2   = (const float*)d_in[8];
    const float* r2   = (const float*)d_in[9];
    const float* b2   = (const float*)d_in[10];
    const float* g2   = (const float*)d_in[11];
    const float* be2  = (const float*)d_in[12];
    const float* cw   = (const float*)d_in[13];
    const float* cb   = (const float*)d_in[14];
    float* out = (float*)d_out;

    cudaFuncSetAttribute(gemm_tc_kernel,
                         cudaFuncAttributeMaxDynamicSharedMemorySize, SMEM_BYTES);

    dim3 gemm_grid(GEMM_TILES, 2);
    int scatter_blocks  = (EE * 32 + 255) / 256;
    int bn_apply_blocks = (NN * HF + 255) / 256;
    int cls_blocks      = (NN * 32 + 255) / 256;
    int splitx_blocks   = (NN * HF + 255) / 256;
    int splitw_blocks   = (9 * 16384 + 255) / 256;
    int edge_blocks     = (EE + 255) / 256;

    // ---- graph prep (shared by both layers) ----
    zero_deg_sums_kernel<<<(NN * RR + 255) / 256, 256>>>();
    deg_count_kernel<<<edge_blocks, 256>>>(ei, et);
    prefix_kernel<<<1, 32>>>();
    place_kernel<<<edge_blocks, 256>>>(ei, et);

    // ---- layer 1 ----
    split_w_kernel<<<splitw_blocks, 256>>>(w1, r1);
    split_x_kernel<<<splitx_blocks, 256>>>(x);
    gemm_tc_kernel<<<gemm_grid, 128, SMEM_BYTES>>>(b1);
    scatter_kernel<<<scatter_blocks, 256>>>();
    bn_stats_kernel<<<256, 256>>>();
    bn_apply_kernel<<<bn_apply_blocks, 256>>>(g1, be1);

    // ---- layer 2 (degree + buckets reused) ----
    zero_sums_kernel<<<1, 128>>>();
    split_w_kernel<<<splitw_blocks, 256>>>(w2, r2);
    gemm_tc_kernel<<<gemm_grid, 128, SMEM_BYTES>>>(b2);
    scatter_kernel<<<scatter_blocks, 256>>>();
    bn_stats_kernel<<<256, 256>>>();
    bn_apply_kernel<<<bn_apply_blocks, 256>>>(g2, be2);

    // ---- classifier ----
    classifier_kernel<<<cls_blocks, 256>>>(cw, cb, out);
}

// round 5
// speedup vs baseline: 1.8626x; 1.8626x over previous
#include <cuda_runtime.h>
#include <cuda_bf16.h>
#include <cstdint>

#define NN   50000
#define EE   800000
#define INF  128
#define HF   128
#define RR   8
#define OUTF 2
#define BN_EPS 1e-5f
#define GEMM_TILES ((NN + 127) / 128)   // 391

// ---------------- scratch (device globals; no allocation allowed) ----------
__device__ float g_xw[(size_t)RR * NN * HF];        // [R][N][H] transformed
__device__ float g_agg[(size_t)NN * HF];            // pre-BN layer output
__device__ __nv_bfloat16 g_xhi[(size_t)NN * HF];    // bf16 hi split of acts
__device__ __nv_bfloat16 g_xlo[(size_t)NN * HF];    // bf16 lo split
__device__ __nv_bfloat16 g_whi[9 * 128 * 128];      // [mat][n][k] W^T, hi
__device__ __nv_bfloat16 g_wlo[9 * 128 * 128];      // lo
__device__ int   g_deg[NN * RR];
__device__ float g_sum[HF];
__device__ float g_sumsq[HF];
// edge bucketing (by relation type)
__device__ int   g_tcnt[RR];
__device__ int   g_tcur[RR];
__device__ int   g_epack[EE];       // src | (type<<16)
__device__ int   g_etgt[EE];

// ======================= small helpers ======================================
__device__ __forceinline__ uint32_t smem_to_u32(const void* p) {
    uint32_t a;
    asm("{ .reg .u64 t; cvta.to.shared.u64 t, %1; cvt.u32.u64 %0, t; }"
        : "=r"(a) : "l"(p));
    return a;
}
__device__ __forceinline__ void cp16(uint32_t dst, const void* src) {
    asm volatile("cp.async.cg.shared.global [%0], [%1], 16;"
                 :: "r"(dst), "l"(__cvta_generic_to_global(src)));
}
__device__ __forceinline__ void mma_bf16(float d[4], const uint32_t a[4],
                                         const uint32_t b[2]) {
    asm volatile(
        "mma.sync.aligned.m16n8k16.row.col.f32.bf16.bf16.f32 "
        "{%0,%1,%2,%3}, {%4,%5,%6,%7}, {%8,%9}, {%0,%1,%2,%3};"
        : "+f"(d[0]), "+f"(d[1]), "+f"(d[2]), "+f"(d[3])
        : "r"(a[0]), "r"(a[1]), "r"(a[2]), "r"(a[3]), "r"(b[0]), "r"(b[1]));
}

// =============== SMEM layout (u32 units), stride 68 u32 = 136 bf16 ==========
#define SWU    68
#define AH_U   0
#define AL_U   (128 * SWU)                 // 8704
#define B0_U   (2 * 128 * SWU)             // 17408
#define B1_U   (B0_U + 128 * SWU)          // 26112
#define SMEM_U32S   (B1_U + 128 * SWU)     // 34816
#define SMEM_BYTES  (SMEM_U32S * 4)        // 139264

// prefetch one 128x128 bf16 tile (row-major [n][k]) into padded smem
__device__ __forceinline__ void prefetch_B(uint32_t sb, int bofs_u,
                                           const __nv_bfloat16* W) {
    int tid = threadIdx.x;
#pragma unroll
    for (int i = 0; i < 8; i++) {
        int e = i * 256 + tid;            // 0..2047 uint4s
        int row = e >> 4;                 // 0..127
        int q   = e & 15;                 // uint4 (8 bf16) within row
        cp16(sb + (uint32_t)(bofs_u + row * SWU + q * 4) * 4, W + row * 128 + q * 8);
    }
}

// one bf16 pass: D += A(smem,[m][k]) x B(smem,[n][k])^T over K=128
__device__ __forceinline__ void do_pass(const uint32_t* __restrict__ As,
                                        const uint32_t* __restrict__ Bs,
                                        float d[4][4][4], int wm, int wn,
                                        int lr, int lc) {
#pragma unroll
    for (int ks = 0; ks < 8; ks++) {
        int k0 = ks * 8;                  // u32 offset for k = ks*16
        uint32_t a[4][4], b[4][2];
#pragma unroll
        for (int mt = 0; mt < 4; mt++) {
            const uint32_t* p = As + (wm * 64 + mt * 16 + lr) * SWU + k0 + lc;
            a[mt][0] = p[0];
            a[mt][1] = p[8 * SWU];
            a[mt][2] = p[4];
            a[mt][3] = p[8 * SWU + 4];
        }
#pragma unroll
        for (int nt = 0; nt < 4; nt++) {
            const uint32_t* p = Bs + (wn * 32 + nt * 8 + lr) * SWU + k0 + lc;
            b[nt][0] = p[0];
            b[nt][1] = p[4];
        }
#pragma unroll
        for (int mt = 0; mt < 4; mt++)
#pragma unroll
            for (int nt = 0; nt < 4; nt++) mma_bf16(d[mt][nt], a[mt], b[nt]);
    }
}

// ================== bf16 tensor GEMM: 9 matrices per M-tile =================
// D[m,n] = sum_k A[m,k]*B[n,k], 3-term bf16 (hi*hi + lo*hi + hi*lo).
// grid = 391 (128-row M tiles); 256 threads; mats 0..7 -> g_xw; 8 -> g_agg+bias.
__global__ void __launch_bounds__(256, 1) gemm_tc_kernel(const float* __restrict__ bias) {
    extern __shared__ uint32_t smu[];
    uint32_t sb = smem_to_u32(smu);
    const int tid = threadIdx.x;
    const int wid = tid >> 5, lane = tid & 31;
    const int wm = wid & 1, wn = wid >> 1;       // 2 x 4 warp grid (64x32 tiles)
    const int lr = lane >> 2, lc = lane & 3;
    const int m0 = blockIdx.x * 128;

    // A tiles (hi/lo) resident for whole CTA; zero rows past NN
#pragma unroll
    for (int i = 0; i < 8; i++) {
        int e = i * 256 + tid;
        int row = e >> 4, q = e & 15;
        uint32_t dh = sb + (uint32_t)(AH_U + row * SWU + q * 4) * 4;
        uint32_t dl = sb + (uint32_t)(AL_U + row * SWU + q * 4) * 4;
        if (m0 + row < NN) {
            cp16(dh, g_xhi + (size_t)(m0 + row) * 128 + q * 8);
            cp16(dl, g_xlo + (size_t)(m0 + row) * 128 + q * 8);
        } else {
            uint4 z = make_uint4(0, 0, 0, 0);
            *reinterpret_cast<uint4*>(smu + AH_U + row * SWU + q * 4) = z;
            *reinterpret_cast<uint4*>(smu + AL_U + row * SWU + q * 4) = z;
        }
    }
    prefetch_B(sb, B0_U, g_whi);    // B_hi(mat 0)
    asm volatile("cp.async.commit_group;" ::: "memory");
    asm volatile("cp.async.wait_group 0;" ::: "memory");
    __syncthreads();

    float d[4][4][4];
#pragma unroll
    for (int mt = 0; mt < 4; mt++)
#pragma unroll
        for (int nt = 0; nt < 4; nt++)
#pragma unroll
            for (int j = 0; j < 4; j++) d[mt][nt][j] = 0.f;

    const uint32_t* Ah = smu + AH_U;
    const uint32_t* Al = smu + AL_U;
    int stage = 0;
    // 18 tiles: even t = B_hi(t/2) [Ahi & Alo passes], odd t = B_lo(t/2) [Ahi pass]
    for (int t = 0; t < 18; t++) {
        if (t + 1 < 18) {
            int nm = (t + 1) >> 1;
            const __nv_bfloat16* Wn =
                ((t + 1) & 1) ? (g_wlo + nm * 16384) : (g_whi + nm * 16384);
            prefetch_B(sb, stage ? B0_U : B1_U, Wn);
        }
        asm volatile("cp.async.commit_group;" ::: "memory");

        const uint32_t* Bs = smu + (stage ? B1_U : B0_U);
        do_pass(Ah, Bs, d, wm, wn, lr, lc);               // a_hi x b
        if (!(t & 1)) do_pass(Al, Bs, d, wm, wn, lr, lc); // a_lo x b_hi

        if (t & 1) {
            int mat = t >> 1;
            float* gbase = (mat < 8) ? (g_xw + (size_t)mat * NN * HF) : g_agg;
#pragma unroll
            for (int mt = 0; mt < 4; mt++) {
                int r0 = m0 + wm * 64 + mt * 16 + lr;
#pragma unroll
                for (int nt = 0; nt < 4; nt++) {
                    int col = wn * 32 + nt * 8 + lc * 2;
                    float b0 = 0.f, b1 = 0.f;
                    if (mat == 8) { b0 = bias[col]; b1 = bias[col + 1]; }
                    if (r0 < NN)
                        *reinterpret_cast<float2*>(gbase + (size_t)r0 * HF + col) =
                            make_float2(d[mt][nt][0] + b0, d[mt][nt][1] + b1);
                    if (r0 + 8 < NN)
                        *reinterpret_cast<float2*>(gbase + (size_t)(r0 + 8) * HF + col) =
                            make_float2(d[mt][nt][2] + b0, d[mt][nt][3] + b1);
#pragma unroll
                    for (int j = 0; j < 4; j++) d[mt][nt][j] = 0.f;
                }
            }
        }
        asm volatile("cp.async.wait_group 0;" ::: "memory");
        __syncthreads();
        stage ^= 1;
    }
}

// ======================= prep kernels ========================================
__global__ void split_x_kernel(const float* __restrict__ x_in) {
    size_t idx = (size_t)blockIdx.x * blockDim.x + threadIdx.x;
    if (idx >= (size_t)NN * HF) return;
    float v = x_in[idx];
    __nv_bfloat16 h = __float2bfloat16_rn(v);
    g_xhi[idx] = h;
    g_xlo[idx] = __float2bfloat16_rn(v - __bfloat162float(h));
}

// transpose W[mat][k][n] -> [mat][n][k], split hi/lo bf16. mat 8 = root.
__global__ void split_w_kernel(const float* __restrict__ w, const float* __restrict__ root) {
    int idx = blockIdx.x * blockDim.x + threadIdx.x;
    if (idx >= 9 * 16384) return;
    int mat = idx >> 14;
    int n = (idx >> 7) & 127;
    int k = idx & 127;
    float v = (mat < 8) ? w[(mat << 14) + (k << 7) + n] : root[(k << 7) + n];
    __nv_bfloat16 h = __float2bfloat16_rn(v);
    g_whi[idx] = h;
    g_wlo[idx] = __float2bfloat16_rn(v - __bfloat162float(h));
}

// ======================= graph preprocessing =================================
__global__ void zero_deg_sums_kernel() {
    int idx = blockIdx.x * blockDim.x + threadIdx.x;
    if (idx < NN * RR) g_deg[idx] = 0;
    if (idx < HF) { g_sum[idx] = 0.f; g_sumsq[idx] = 0.f; }
    if (idx < RR) g_tcnt[idx] = 0;
}
__global__ void zero_sums_kernel() {
    int idx = threadIdx.x;
    if (idx < HF) { g_sum[idx] = 0.f; g_sumsq[idx] = 0.f; }
}
// per-(node,rel) degree + block-aggregated type histogram (8 global atomics/blk)
__global__ void deg_count_kernel(const int* __restrict__ ei, const int* __restrict__ et) {
    __shared__ int hcnt[RR];
    int tid = threadIdx.x;
    if (tid < RR) hcnt[tid] = 0;
    __syncthreads();
    int e = blockIdx.x * blockDim.x + tid;
    if (e < EE) {
        int tgt = ei[EE + e];
        int t   = et[e];
        atomicAdd(&g_deg[tgt * RR + t], 1);
        atomicAdd(&hcnt[t], 1);
    }
    __syncthreads();
    if (tid < RR && hcnt[tid] > 0) atomicAdd(&g_tcnt[tid], hcnt[tid]);
}
__global__ void prefix_kernel() {
    if (threadIdx.x == 0) {
        int acc = 0;
        for (int r = 0; r < RR; r++) {
            g_tcur[r] = acc;
            acc += g_tcnt[r];
        }
    }
}
// block-aggregated placement: SMEM rank + one range reservation per type/blk
__global__ void place_kernel(const int* __restrict__ ei, const int* __restrict__ et) {
    __shared__ int scnt[RR], sbase[RR];
    int tid = threadIdx.x;
    if (tid < RR) scnt[tid] = 0;
    __syncthreads();
    int e = blockIdx.x * blockDim.x + tid;
    int rank = 0, t = 0, src = 0, tgt = 0;
    bool valid = (e < EE);
    if (valid) {
        src = ei[e];
        tgt = ei[EE + e];
        t   = et[e];
        rank = atomicAdd(&scnt[t], 1);
    }
    __syncthreads();
    if (tid < RR) sbase[tid] = (scnt[tid] > 0) ? atomicAdd(&g_tcur[tid], scnt[tid]) : 0;
    __syncthreads();
    if (valid) {
        int pos = sbase[t] + rank;
        g_epack[pos] = src | (t << 16);
        g_etgt[pos]  = tgt;
    }
}

// ---------------- edge scatter: one warp per (type-sorted) edge -------------
__global__ void scatter_kernel() {
    int w = (blockIdx.x * blockDim.x + threadIdx.x) >> 5;
    if (w >= EE) return;
    int lane = threadIdx.x & 31;
    int p   = g_epack[w];
    int src = p & 0xFFFF;
    int t   = p >> 16;
    int tgt = g_etgt[w];
    float inv = 1.0f / (float)g_deg[tgt * RR + t];
    float4 v = *reinterpret_cast<const float4*>(
        g_xw + ((size_t)t * NN + src) * HF + lane * 4);
    float* dst = g_agg + (size_t)tgt * HF + lane * 4;
    asm volatile("red.global.add.v4.f32 [%0], {%1, %2, %3, %4};"
        :: "l"(__cvta_generic_to_global(dst)),
           "f"(v.x * inv), "f"(v.y * inv), "f"(v.z * inv), "f"(v.w * inv)
        : "memory");
}

// ---------------- BN stats / apply ------------------------------------------
__global__ void bn_stats_kernel() {
    int c = threadIdx.x & 127;
    int rstart = blockIdx.x * (blockDim.x >> 7) + (threadIdx.x >> 7);
    int rstep  = gridDim.x * (blockDim.x >> 7);
    float s = 0.f, ss = 0.f;
    for (int r = rstart; r < NN; r += rstep) {
        float v = g_agg[(size_t)r * HF + c];
        s += v;
        ss += v * v;
    }
    atomicAdd(&g_sum[c], s);
    atomicAdd(&g_sumsq[c], ss);
}
// BN + ReLU, emitting bf16 hi/lo splits directly
__global__ void bn_apply_kernel(const float* __restrict__ gamma,
                                const float* __restrict__ beta) {
    int idx = blockIdx.x * blockDim.x + threadIdx.x;
    if (idx >= NN * HF) return;
    int c = idx & 127;
    const float invN = 1.0f / (float)NN;
    float mean = g_sum[c] * invN;
    float var  = fmaxf(g_sumsq[c] * invN - mean * mean, 0.f);
    float v = (g_agg[idx] - mean) * rsqrtf(var + BN_EPS) * gamma[c] + beta[c];
    v = fmaxf(v, 0.f);
    __nv_bfloat16 h = __float2bfloat16_rn(v);
    g_xhi[idx] = h;
    g_xlo[idx] = __float2bfloat16_rn(v - __bfloat162float(h));
}

// ---------------- classifier: out[N,2] = (hi+lo) @ cw + cb ------------------
__global__ void classifier_kernel(const float* __restrict__ cw,
                                  const float* __restrict__ cb,
                                  float* __restrict__ out) {
    __shared__ float wsm[HF * OUTF];
    if (threadIdx.x < HF * OUTF) wsm[threadIdx.x] = cw[threadIdx.x];
    __syncthreads();
    int w = (blockIdx.x * blockDim.x + threadIdx.x) >> 5;
    if (w >= NN) return;
    int lane = threadIdx.x & 31;
    // 4 values per lane: hi + lo reconstruct
    const __nv_bfloat162* ph = reinterpret_cast<const __nv_bfloat162*>(
        g_xhi + (size_t)w * HF + lane * 4);
    const __nv_bfloat162* pl = reinterpret_cast<const __nv_bfloat162*>(
        g_xlo + (size_t)w * HF + lane * 4);
    __nv_bfloat162 h0 = ph[0], h1 = ph[1], l0 = pl[0], l1 = pl[1];
    float vx = __bfloat162float(h0.x) + __bfloat162float(l0.x);
    float vy = __bfloat162float(h0.y) + __bfloat162float(l0.y);
    float vz = __bfloat162float(h1.x) + __bfloat162float(l1.x);
    float vw = __bfloat162float(h1.y) + __bfloat162float(l1.y);
    int c = lane * 4;
    float o0 = vx * wsm[(c + 0) * 2]     + vy * wsm[(c + 1) * 2]
             + vz * wsm[(c + 2) * 2]     + vw * wsm[(c + 3) * 2];
    float o1 = vx * wsm[(c + 0) * 2 + 1] + vy * wsm[(c + 1) * 2 + 1]
             + vz * wsm[(c + 2) * 2 + 1] + vw * wsm[(c + 3) * 2 + 1];
#pragma unroll
    for (int off = 16; off > 0; off >>= 1) {
        o0 += __shfl_down_sync(0xFFFFFFFFu, o0, off);
        o1 += __shfl_down_sync(0xFFFFFFFFu, o1, off);
    }
    if (lane == 0) {
        out[(size_t)w * 2 + 0] = o0 + cb[0];
        out[(size_t)w * 2 + 1] = o1 + cb[1];
    }
}

// ================================ launch =====================================
extern "C" void kernel_launch(void* const* d_in, const int* in_sizes, int n_in,
                              void* d_out, int out_size) {
    const float* x    = (const float*)d_in[0];
    const int*   ei   = (const int*)d_in[1];
    const int*   et   = (const int*)d_in[2];
    const float* w1   = (const float*)d_in[3];
    const float* r1   = (const float*)d_in[4];
    const float* b1   = (const float*)d_in[5];
    const float* g1   = (const float*)d_in[6];
    const float* be1  = (const float*)d_in[7];
    const float* w2   = (const float*)d_in[8];
    const float* r2   = (const float*)d_in[9];
    const float* b2   = (const float*)d_in[10];
    const float* g2   = (const float*)d_in[11];
    const float* be2  = (const float*)d_in[12];
    const float* cw   = (const float*)d_in[13];
    const float* cb   = (const float*)d_in[14];
    float* out = (float*)d_out;

    cudaFuncSetAttribute(gemm_tc_kernel,
                         cudaFuncAttributeMaxDynamicSharedMemorySize, SMEM_BYTES);

    int scatter_blocks  = (EE * 32 + 255) / 256;
    int bn_apply_blocks = (NN * HF + 255) / 256;
    int cls_blocks      = (NN * 32 + 255) / 256;
    int splitx_blocks   = (NN * HF + 255) / 256;
    int splitw_blocks   = (9 * 16384 + 255) / 256;
    int edge_blocks     = (EE + 255) / 256;

    // ---- graph prep (shared by both layers) ----
    zero_deg_sums_kernel<<<(NN * RR + 255) / 256, 256>>>();
    deg_count_kernel<<<edge_blocks, 256>>>(ei, et);
    prefix_kernel<<<1, 32>>>();
    place_kernel<<<edge_blocks, 256>>>(ei, et);

    // ---- layer 1 ----
    split_w_kernel<<<splitw_blocks, 256>>>(w1, r1);
    split_x_kernel<<<splitx_blocks, 256>>>(x);
    gemm_tc_kernel<<<GEMM_TILES, 256, SMEM_BYTES>>>(b1);
    scatter_kernel<<<scatter_blocks, 256>>>();
    bn_stats_kernel<<<256, 256>>>();
    bn_apply_kernel<<<bn_apply_blocks, 256>>>(g1, be1);

    // ---- layer 2 (degree + buckets reused) ----
    zero_sums_kernel<<<1, 128>>>();
    split_w_kernel<<<splitw_blocks, 256>>>(w2, r2);
    gemm_tc_kernel<<<GEMM_TILES, 256, SMEM_BYTES>>>(b2);
    scatter_kernel<<<scatter_blocks, 256>>>();
    bn_stats_kernel<<<256, 256>>>();
    bn_apply_kernel<<<bn_apply_blocks, 256>>>(g2, be2);

    // ---- classifier ----
    classifier_kernel<<<cls_blocks, 256>>>(cw, cb, out);
}